// round 15
// baseline (speedup 1.0000x reference)
#include <cuda_runtime.h>
#include <cuda_fp16.h>
#include <cstdint>
#include <math.h>

#define TT 128
#define BB 512
#define DD 300
#define DPAD 320
#define HH 512
#define G3 1536

#define SO_A   0
#define SO_BHI 16384
#define SO_BLO 40960
#define STAGE  65536
#define SMEM_GI (3 * STAGE)

#define PSO_W   0
#define PSO_WLO 98304
#define PSO_A   196608
#define SMEM_P  229376

__device__ __forceinline__ uint32_t smem_u32(const void* p) {
    uint32_t a;
    asm("{ .reg .u64 t; cvta.to.shared.u64 t, %1; cvt.u32.u64 %0, t; }" : "=r"(a) : "l"(p));
    return a;
}
__device__ __forceinline__ void cp16(uint32_t s, const void* g) {
    asm volatile("cp.async.cg.shared.global [%0], [%1], 16;" :: "r"(s), "l"(g));
}
__device__ __forceinline__ void ldm4(uint32_t* r, uint32_t a) {
    asm volatile("ldmatrix.sync.aligned.m8n8.x4.shared.b16 {%0,%1,%2,%3}, [%4];"
                 : "=r"(r[0]), "=r"(r[1]), "=r"(r[2]), "=r"(r[3]) : "r"(a));
}
__device__ __forceinline__ void ldm2(uint32_t* r, uint32_t a) {
    asm volatile("ldmatrix.sync.aligned.m8n8.x2.shared.b16 {%0,%1}, [%2];"
                 : "=r"(r[0]), "=r"(r[1]) : "r"(a));
}
__device__ __forceinline__ void mma16816(float* c, const uint32_t* a, const uint32_t* b) {
    asm volatile("mma.sync.aligned.m16n8k16.row.col.f32.f16.f16.f32 "
        "{%0,%1,%2,%3}, {%4,%5,%6,%7}, {%8,%9}, {%0,%1,%2,%3};"
        : "+f"(c[0]), "+f"(c[1]), "+f"(c[2]), "+f"(c[3])
        : "r"(a[0]), "r"(a[1]), "r"(a[2]), "r"(a[3]), "r"(b[0]), "r"(b[1]));
}
__device__ __forceinline__ uint32_t swz(uint32_t o) { return o ^ ((o >> 3) & 0x70); }
__device__ __forceinline__ float sigmoidf_(float x) { return 1.f / (1.f + expf(-x)); }

__device__ __align__(16) __half g_x[(size_t)TT * BB * DPAD];
__device__ __align__(16) __half g_Wih0[2][2][(size_t)G3 * DPAD];
__device__ __align__(16) __half g_Wih[2][2][2][(size_t)G3 * HH];
__device__ __align__(16) __half g_Whh[2][3][2][(size_t)G3 * HH];   // 96-row gate perm
__device__ float g_bih[2][3][G3];
__device__ float g_bhh[2][3][G3];
__device__ __align__(16) __half g_h[2][(size_t)TT * BB * HH];
__device__ __align__(16) float g_gi[2][(size_t)TT * BB * G3];
// per-(dir,mblk,wm) group counters, 128B apart: 2*4*4 = 32 counters
__device__ unsigned g_cnt[32 * 32];

// ---------------- prep ----------------
__global__ void prep_x(const float* __restrict__ src) {
    if (blockIdx.x == 0)
        for (int i = threadIdx.x; i < 32 * 32; i += blockDim.x) g_cnt[i] = 0;
    const size_t total = (size_t)TT * BB * DPAD;
    for (size_t i = (size_t)blockIdx.x * blockDim.x + threadIdx.x; i < total;
         i += (size_t)gridDim.x * blockDim.x) {
        int r = (int)(i / DPAD), k = (int)(i % DPAD);
        g_x[i] = __float2half_rn((k < DD) ? src[(size_t)r * DD + k] : 0.f);
    }
}

__global__ void prep_w_all(
    const float* __restrict__ fWih0, const float* __restrict__ bWih0,
    const float* __restrict__ fWih,  const float* __restrict__ bWih,
    const float* __restrict__ fWhh0, const float* __restrict__ bWhh0,
    const float* __restrict__ fWhh,  const float* __restrict__ bWhh)
{
    const int ti = blockIdx.y;
    const float* src; int dir, kind, l;
    switch (ti) {
        case 0:  src = fWih0;              dir = 0; kind = 0; l = 0; break;
        case 1:  src = bWih0;              dir = 1; kind = 0; l = 0; break;
        case 2:  src = fWih;               dir = 0; kind = 1; l = 0; break;
        case 3:  src = fWih + (size_t)G3 * HH; dir = 0; kind = 1; l = 1; break;
        case 4:  src = bWih;               dir = 1; kind = 1; l = 0; break;
        case 5:  src = bWih + (size_t)G3 * HH; dir = 1; kind = 1; l = 1; break;
        case 6:  src = fWhh0;              dir = 0; kind = 2; l = 0; break;
        case 7:  src = fWhh;               dir = 0; kind = 2; l = 1; break;
        case 8:  src = fWhh + (size_t)G3 * HH; dir = 0; kind = 2; l = 2; break;
        case 9:  src = bWhh0;              dir = 1; kind = 2; l = 0; break;
        case 10: src = bWhh;               dir = 1; kind = 2; l = 1; break;
        default: src = bWhh + (size_t)G3 * HH; dir = 1; kind = 2; l = 2; break;
    }
    int K, Kpad; __half *hi, *lo;
    if (kind == 0)      { K = DD; Kpad = DPAD; hi = g_Wih0[dir][0]; lo = g_Wih0[dir][1]; }
    else if (kind == 1) { K = HH; Kpad = HH;   hi = g_Wih[dir][l][0]; lo = g_Wih[dir][l][1]; }
    else                { K = HH; Kpad = HH;   hi = g_Whh[dir][l][0]; lo = g_Whh[dir][l][1]; }
    const size_t total = (size_t)G3 * Kpad;
    for (size_t i = (size_t)blockIdx.x * blockDim.x + threadIdx.x; i < total;
         i += (size_t)gridDim.x * blockDim.x) {
        int r = (int)(i / Kpad), k = (int)(i % Kpad);
        int sr;
        if (kind == 2) { int rem = r % 96;  sr = (rem >> 5) * HH + (r / 96) * 32 + (rem & 31); }
        else           { int rem = r % 192; sr = (rem >> 6) * HH + (r / 192) * 64 + (rem & 63); }
        float v = (k < K) ? src[(size_t)sr * K + k] : 0.f;
        __half h = __float2half_rn(v);
        hi[i] = h; lo[i] = __float2half_rn(v - __half2float(h));
    }
}

__global__ void prep_b_all(
    const float* __restrict__ fbih0, const float* __restrict__ bbih0,
    const float* __restrict__ fbih,  const float* __restrict__ bbih,
    const float* __restrict__ fbhh0, const float* __restrict__ bbhh0,
    const float* __restrict__ fbhh,  const float* __restrict__ bbhh)
{
    const int ti = blockIdx.y;
    const int which = ti / 6;
    const int dir = (ti % 6) / 3, l = ti % 3;
    const float* src;
    if (which == 0) {
        if (l == 0) src = dir ? bbih0 : fbih0;
        else        src = (dir ? bbih : fbih) + (size_t)(l - 1) * G3;
    } else {
        if (l == 0) src = dir ? bbhh0 : fbhh0;
        else        src = (dir ? bbhh : fbhh) + (size_t)(l - 1) * G3;
    }
    int r = blockIdx.x * blockDim.x + threadIdx.x;
    if (r < G3) {
        int rem = r % 192;
        float v = src[(rem >> 6) * HH + (r / 192) * 64 + (rem & 63)];
        if (which == 0) g_bih[dir][l][r] = v; else g_bhh[dir][l][r] = v;
    }
}

// ================= gi GEMM path (unchanged from R14) =================
__device__ __forceinline__ void load_tile(
    uint32_t sbuf, const char* A, size_t lda,
    const char* Wh, const char* Wl, size_t ldw, int kt, int tid)
{
    const size_t kb = (size_t)kt * 128;
    for (int i = tid; i < 1024; i += 512) {
        int r = i >> 3, ch = (i & 7) * 16;
        uint32_t so = swz((uint32_t)(r * 128 + ch));
        cp16(sbuf + SO_A + so, A + (size_t)r * lda + kb + ch);
    }
    for (int i = tid; i < 1536; i += 512) {
        int r = i >> 3, ch = (i & 7) * 16;
        uint32_t so = swz((uint32_t)(r * 128 + ch));
        const size_t go = (size_t)r * ldw + kb + ch;
        cp16(sbuf + SO_BHI + so, Wh + go);
        cp16(sbuf + SO_BLO + so, Wl + go);
    }
    asm volatile("cp.async.commit_group;" ::: "memory");
}

__device__ __forceinline__ void compute_tile(
    uint32_t sbuf, int wm, int wn, int lane, float (&acc)[2][3][2][4])
{
    const int arow = wm * 32 + (lane & 15);
    const int acolsel = (lane >> 4) * 16;
    const int mat = lane >> 3;
    const int brow_in = (mat >> 1) * 8 + (lane & 7);
    const int bcol = (mat & 1) * 16;
    #pragma unroll
    for (int kk = 0; kk < 4; kk++) {
        uint32_t ah[2][4];
        #pragma unroll
        for (int mt = 0; mt < 2; mt++) {
            uint32_t o = swz((uint32_t)((arow + mt * 16) * 128 + kk * 32 + acolsel));
            ldm4(ah[mt], sbuf + SO_A + o);
        }
        #pragma unroll
        for (int g = 0; g < 3; g++) {
            uint32_t o = swz((uint32_t)((g * 64 + wn * 16 + brow_in) * 128 + kk * 32 + bcol));
            uint32_t bh[4], bl[4];
            ldm4(bh, sbuf + SO_BHI + o);
            ldm4(bl, sbuf + SO_BLO + o);
            #pragma unroll
            for (int mt = 0; mt < 2; mt++) {
                #pragma unroll
                for (int q = 0; q < 2; q++) {
                    float* c = acc[mt][g][q];
                    mma16816(c, ah[mt], &bh[q * 2]);
                    mma16816(c, ah[mt], &bl[q * 2]);
                }
            }
        }
    }
}

__global__ __launch_bounds__(512) void gi_mma(int l)
{
    extern __shared__ char smem[];
    const uint32_t sb = smem_u32(smem);
    const int tid = threadIdx.x, lane = tid & 31, wid = tid >> 5;
    const int wm = wid & 3, wn = wid >> 2;
    const int dir = blockIdx.z, nblk = blockIdx.x, m0 = blockIdx.y * 128;

    const __half *A, *Wh, *Wl;
    int ld, NK; size_t arow0;
    if (l == 0) {
        ld = DPAD; NK = 5;
        int t = m0 / BB, tt = dir ? (TT - 1 - t) : t;
        arow0 = (size_t)tt * BB + (m0 % BB);
        A = g_x; Wh = g_Wih0[dir][0]; Wl = g_Wih0[dir][1];
    } else {
        ld = HH; NK = 8; arow0 = m0;
        A = g_h[dir];
        Wh = g_Wih[dir][l - 1][0]; Wl = g_Wih[dir][l - 1][1];
    }
    const size_t ldb = (size_t)ld * 2;
    const char* Ab  = (const char*)(A + arow0 * ld);
    const char* Whb = (const char*)(Wh + (size_t)nblk * 192 * ld);
    const char* Wlb = (const char*)(Wl + (size_t)nblk * 192 * ld);

    float acc[2][3][2][4];
    #pragma unroll
    for (int a = 0; a < 2; a++)
        #pragma unroll
        for (int b = 0; b < 3; b++)
            #pragma unroll
            for (int c = 0; c < 2; c++)
                #pragma unroll
                for (int d = 0; d < 4; d++) acc[a][b][c][d] = 0.f;

    uint32_t sstage[3] = { sb, sb + STAGE, sb + 2 * STAGE };
    load_tile(sstage[0], Ab, ldb, Whb, Wlb, ldb, 0, tid);
    load_tile(sstage[1], Ab, ldb, Whb, Wlb, ldb, 1, tid);
    int slot = 0;
    for (int kt = 0; kt < NK; kt++) {
        if (kt + 1 < NK) asm volatile("cp.async.wait_group 1;" ::: "memory");
        else             asm volatile("cp.async.wait_group 0;" ::: "memory");
        __syncthreads();
        if (kt + 2 < NK) {
            int ns = slot + 2; if (ns >= 3) ns -= 3;
            load_tile(sstage[ns], Ab, ldb, Whb, Wlb, ldb, kt + 2, tid);
        }
        compute_tile(sstage[slot], wm, wn, lane, acc);
        if (++slot == 3) slot = 0;
    }

    float* gout = g_gi[dir];
    const float* bias = g_bih[dir][l];
    #pragma unroll
    for (int mt = 0; mt < 2; mt++) {
        const int r0 = m0 + wm * 32 + mt * 16 + (lane >> 2);
        #pragma unroll
        for (int g = 0; g < 3; g++)
            #pragma unroll
            for (int q = 0; q < 2; q++) {
                const int col = nblk * 192 + g * 64 + wn * 16 + q * 8 + (lane & 3) * 2;
                const float b0 = bias[col], b1 = bias[col + 1];
                const float* c = acc[mt][g][q];
                *(float2*)(gout + (size_t)r0 * G3 + col) = make_float2(c[0] + b0, c[1] + b1);
                *(float2*)(gout + (size_t)(r0 + 8) * G3 + col) = make_float2(c[2] + b0, c[3] + b1);
            }
    }
}

// ================= persistent recurrent kernel (fully group-decoupled) ================
// Group = (dir, mblk, wm): 4 warps on one SMSP, owns h rows [m0+wm*32, +32).
// Inter-CTA sync: per-(dir,mblk,wm) counter; 16 producers (nblk) per counter per step.
// No CTA-wide __syncthreads in steady state.
__device__ __forceinline__ void p_loadA_grp(uint32_t abuf, const char* Ab, int kt, int gidx)
{
    const size_t kb = (size_t)kt * 128;
    #pragma unroll
    for (int j = 0; j < 2; j++) {
        int i = gidx + j * 128;
        int r = i >> 3, ch = (i & 7) * 16;
        cp16(abuf + swz((uint32_t)(r * 128 + ch)), Ab + (size_t)r * 1024 + kb + ch);
    }
    asm volatile("cp.async.commit_group;" ::: "memory");
}

__device__ __forceinline__ void p_compute(
    uint32_t sb, uint32_t abuf, int kt, int wn, int lane, float (&acc)[2][3][4])
{
    const int arow = lane & 15;
    const int acolsel = (lane >> 4) * 16;
    const int l4 = lane & 15;
    const int brow_in = l4 & 7;
    const int bcol = (l4 >> 3) * 16;
    const uint32_t whi = sb + PSO_W   + kt * 12288;
    const uint32_t wlo = sb + PSO_WLO + kt * 12288;
    #pragma unroll
    for (int kk = 0; kk < 4; kk++) {
        uint32_t ah[2][4];
        #pragma unroll
        for (int mt = 0; mt < 2; mt++) {
            uint32_t o = swz((uint32_t)((arow + mt * 16) * 128 + kk * 32 + acolsel));
            ldm4(ah[mt], abuf + o);
        }
        #pragma unroll
        for (int g = 0; g < 3; g++) {
            uint32_t o = swz((uint32_t)((g * 32 + wn * 8 + brow_in) * 128 + kk * 32 + bcol));
            uint32_t bh[2], bl[2];
            ldm2(bh, whi + o);
            ldm2(bl, wlo + o);
            #pragma unroll
            for (int mt = 0; mt < 2; mt++) {
                float* c = acc[mt][g];
                mma16816(c, ah[mt], bh);
                mma16816(c, ah[mt], bl);
            }
        }
    }
}

__device__ __forceinline__ void p_prefetch(
    int dir, int t, int m0, int wm, int lane, int j0, int c0,
    float2 (&Pr)[2][2], float2 (&Pz)[2][2], float2 (&Pn)[2][2], __half2 (&Pp)[2][2])
{
    const float* giP = g_gi[dir] + (size_t)t * BB * G3;
    const __half* Ph = g_h[dir] + (size_t)(t - 1) * BB * HH;
    #pragma unroll
    for (int mt = 0; mt < 2; mt++)
        #pragma unroll
        for (int hf = 0; hf < 2; hf++) {
            const int m = m0 + wm * 32 + mt * 16 + (lane >> 2) + hf * 8;
            const float* gim = giP + (size_t)m * G3;
            Pr[mt][hf] = __ldg((const float2*)(gim + c0));
            Pz[mt][hf] = __ldg((const float2*)(gim + c0 + 64));
            Pn[mt][hf] = __ldg((const float2*)(gim + c0 + 128));
            if (t > 0)
                Pp[mt][hf] = __ldg((const __half2*)(Ph + (size_t)m * HH + j0));
            else
                Pp[mt][hf] = __half2{__half(0.f), __half(0.f)};
        }
}

__global__ __launch_bounds__(512) void gru_persist(int l, unsigned base)
{
    extern __shared__ char smem[];
    const uint32_t sb = smem_u32(smem);
    const int tid = threadIdx.x, lane = tid & 31, wid = tid >> 5;
    const int wm = wid & 3, wn = wid >> 2;
    const int gidx = wn * 32 + lane;
    const int barid = 1 + wm;
    const int bid = blockIdx.x;
    const int dir = bid >> 6, nblk = (bid >> 2) & 15, mblk = bid & 3;
    const int m0 = mblk * 128;
    unsigned* cnt = &g_cnt[((dir * 4 + mblk) * 4 + wm) * 32];
    const bool leader = (wn == 0 && lane == 0);

    // ---- load resident W slice (one-time; CTA-wide sync OK here) ----
    {
        const char* Wh = (const char*)(g_Whh[dir][l][0] + (size_t)nblk * 96 * HH);
        const char* Wl = (const char*)(g_Whh[dir][l][1] + (size_t)nblk * 96 * HH);
        for (int kt = 0; kt < 8; kt++) {
            for (int i = tid; i < 768; i += 512) {
                int r = i >> 3, ch = (i & 7) * 16;
                uint32_t so = swz((uint32_t)(r * 128 + ch));
                size_t go = (size_t)r * 1024 + (size_t)kt * 128 + ch;
                cp16(sb + PSO_W   + kt * 12288 + so, Wh + go);
                cp16(sb + PSO_WLO + kt * 12288 + so, Wl + go);
            }
        }
        asm volatile("cp.async.commit_group;" ::: "memory");
        asm volatile("cp.async.wait_group 0;" ::: "memory");
        __syncthreads();
    }

    const float* bh = g_bhh[dir][l];
    const int j0 = nblk * 32 + wn * 8 + (lane & 3) * 2;
    const int c0 = ((j0 >> 6) * 192) + (j0 & 63);
    const float bhr0 = bh[c0], bhr1 = bh[c0 + 1];
    const float bhz0 = bh[c0 + 64], bhz1 = bh[c0 + 65];
    const float bhn0 = bh[c0 + 128], bhn1 = bh[c0 + 129];

    const uint32_t agrp = sb + PSO_A + wm * 8192;

    float2 Pr[2][2], Pz[2][2], Pn[2][2];
    __half2 Pp[2][2];
    p_prefetch(dir, 0, m0, wm, lane, j0, c0, Pr, Pz, Pn, Pp);

    for (int t = 0; t < TT; t++) {
        float acc[2][3][4];
        #pragma unroll
        for (int a = 0; a < 2; a++)
            #pragma unroll
            for (int b = 0; b < 3; b++)
                #pragma unroll
                for (int d = 0; d < 4; d++) acc[a][b][d] = 0.f;

        if (t > 0) {
            // consumer gate: h(t-1) all cols published by the 16 producer groups
            if (leader) {
                const unsigned tgt = base + (unsigned)t * 16u;
                unsigned v;
                while (true) {
                    asm volatile("ld.global.acquire.gpu.u32 %0, [%1];"
                                 : "=r"(v) : "l"(cnt));
                    if (v >= tgt) break;
                    __nanosleep(64);
                }
            }
            asm volatile("bar.sync %0, 128;" :: "r"(barid) : "memory");

            const char* Ab = (const char*)(g_h[dir]
                + ((size_t)(t - 1) * BB + m0 + wm * 32) * HH);
            p_loadA_grp(agrp, Ab, 0, gidx);
            for (int kt = 0; kt < 8; kt++) {
                asm volatile("cp.async.wait_group 0;" ::: "memory");
                asm volatile("bar.sync %0, 128;" :: "r"(barid) : "memory");
                if (kt + 1 < 8)
                    p_loadA_grp(agrp + ((kt + 1) & 1) * 4096, Ab, kt + 1, gidx);
                p_compute(sb, agrp + (kt & 1) * 4096, kt, wn, lane, acc);
            }
        }

        // ---- epilogue: write h(t) rows (group-local) ----
        __half* Oh = g_h[dir] + (size_t)t * BB * HH;
        #pragma unroll
        for (int mt = 0; mt < 2; mt++) {
            const float* c_r = acc[mt][0];
            const float* c_z = acc[mt][1];
            const float* c_n = acc[mt][2];
            #pragma unroll
            for (int hf = 0; hf < 2; hf++) {
                const int m = m0 + wm * 32 + mt * 16 + (lane >> 2) + hf * 8;
                const float2 gr = Pr[mt][hf];
                const float2 gz = Pz[mt][hf];
                const float2 gn = Pn[mt][hf];
                const float hp0 = __half2float(Pp[mt][hf].x);
                const float hp1 = __half2float(Pp[mt][hf].y);
                const float rg0 = sigmoidf_(gr.x + bhr0 + c_r[hf * 2 + 0]);
                const float rg1 = sigmoidf_(gr.y + bhr1 + c_r[hf * 2 + 1]);
                const float zg0 = sigmoidf_(gz.x + bhz0 + c_z[hf * 2 + 0]);
                const float zg1 = sigmoidf_(gz.y + bhz1 + c_z[hf * 2 + 1]);
                const float ng0 = tanhf(gn.x + rg0 * (c_n[hf * 2 + 0] + bhn0));
                const float ng1 = tanhf(gn.y + rg1 * (c_n[hf * 2 + 1] + bhn1));
                __half2 hh;
                hh.x = __float2half_rn((1.f - zg0) * ng0 + zg0 * hp0);
                hh.y = __float2half_rn((1.f - zg1) * ng1 + zg1 * hp1);
                *(__half2*)(Oh + (size_t)m * HH + j0) = hh;
            }
        }

        // ---- publish h(t) at group scope; prefetch(t+1) is group-local ----
        if (t + 1 < TT) {
            asm volatile("bar.sync %0, 128;" :: "r"(barid) : "memory");
            if (leader) {
                __threadfence();
                atomicAdd(cnt, 1u);
            }
            p_prefetch(dir, t + 1, m0, wm, lane, j0, c0, Pr, Pz, Pn, Pp);
        }
    }
}

// ---------------- projection ----------------
__global__ __launch_bounds__(256) void proj_kernel(
    const float* __restrict__ Wmu, const float* __restrict__ bmu,
    const float* __restrict__ Wlv, const float* __restrict__ blv,
    float* __restrict__ out)
{
    __shared__ float As[16][66];
    __shared__ float Bs[16][66];
    const int which = blockIdx.z;
    const float* W = which ? Wlv : Wmu;
    const float* bias = which ? blv : bmu;
    const int n0 = blockIdx.x * 64, m0 = blockIdx.y * 64;
    const __half* hf = g_h[0] + ((size_t)(TT - 1) * BB + m0) * HH;
    const __half* hb = g_h[1] + ((size_t)(TT - 1) * BB + m0) * HH;
    const int tid = threadIdx.x, tx = tid & 15, ty = tid >> 4;
    float acc[4][4];
    #pragma unroll
    for (int i = 0; i < 4; i++)
        #pragma unroll
        for (int j = 0; j < 4; j++) acc[i][j] = 0.f;

    for (int k0 = 0; k0 < 2 * HH; k0 += 16) {
        #pragma unroll
        for (int i = 0; i < 4; i++) {
            const int e = tid + i * 256;
            const int kk = e & 15, mm = e >> 4;
            const int k = k0 + kk;
            As[kk][mm] = (k < HH) ? __half2float(hf[(size_t)mm * HH + k])
                                  : __half2float(hb[(size_t)mm * HH + k - HH]);
            Bs[kk][mm] = W[(size_t)(n0 + mm) * (2 * HH) + k];
        }
        __syncthreads();
        #pragma unroll
        for (int kk = 0; kk < 16; kk++) {
            float a[4], b[4];
            #pragma unroll
            for (int i = 0; i < 4; i++) a[i] = As[kk][ty * 4 + i];
            #pragma unroll
            for (int j = 0; j < 4; j++) b[j] = Bs[kk][tx * 4 + j];
            #pragma unroll
            for (int i = 0; i < 4; i++)
                #pragma unroll
                for (int j = 0; j < 4; j++) acc[i][j] += a[i] * b[j];
        }
        __syncthreads();
    }
    #pragma unroll
    for (int i = 0; i < 4; i++) {
        const int m = m0 + ty * 4 + i;
        #pragma unroll
        for (int j = 0; j < 4; j++) {
            const int n = n0 + tx * 4 + j;
            out[(size_t)which * BB * HH + (size_t)m * HH + n] = acc[i][j] + bias[n];
        }
    }
}

extern "C" void kernel_launch(void* const* d_in, const int* in_sizes, int n_in,
                              void* d_out, int out_size)
{
    (void)in_sizes; (void)n_in; (void)out_size;
    const float* x       = (const float*)d_in[0];
    const float* fw_Wih0 = (const float*)d_in[2];
    const float* fw_Whh0 = (const float*)d_in[3];
    const float* fw_bih0 = (const float*)d_in[4];
    const float* fw_bhh0 = (const float*)d_in[5];
    const float* fw_Wih  = (const float*)d_in[6];
    const float* fw_Whh  = (const float*)d_in[7];
    const float* fw_bih  = (const float*)d_in[8];
    const float* fw_bhh  = (const float*)d_in[9];
    const float* bw_Wih0 = (const float*)d_in[10];
    const float* bw_Whh0 = (const float*)d_in[11];
    const float* bw_bih0 = (const float*)d_in[12];
    const float* bw_bhh0 = (const float*)d_in[13];
    const float* bw_Wih  = (const float*)d_in[14];
    const float* bw_Whh  = (const float*)d_in[15];
    const float* bw_bih  = (const float*)d_in[16];
    const float* bw_bhh  = (const float*)d_in[17];
    const float* W_mu    = (const float*)d_in[18];
    const float* b_mu    = (const float*)d_in[19];
    const float* W_lv    = (const float*)d_in[20];
    const float* b_lv    = (const float*)d_in[21];
    float* out = (float*)d_out;

    cudaFuncSetAttribute(gi_mma,      cudaFuncAttributeMaxDynamicSharedMemorySize, SMEM_GI);
    cudaFuncSetAttribute(gru_persist, cudaFuncAttributeMaxDynamicSharedMemorySize, SMEM_P);

    prep_x<<<2048, 256>>>(x);
    prep_w_all<<<dim3(256, 12), 256>>>(fw_Wih0, bw_Wih0, fw_Wih, bw_Wih,
                                       fw_Whh0, bw_Whh0, fw_Whh, bw_Whh);
    prep_b_all<<<dim3(6, 12), 256>>>(fw_bih0, bw_bih0, fw_bih, bw_bih,
                                     fw_bhh0, bw_bhh0, fw_bhh, bw_bhh);

    const dim3 ggi(8, (TT * BB) / 128, 2);
    for (int l = 0; l < 3; l++) {
        gi_mma<<<ggi, 512, SMEM_GI>>>(l);
        gru_persist<<<128, 512, SMEM_P>>>(l, (unsigned)(l * 127 * 16));
    }
    proj_kernel<<<dim3(HH / 64, BB / 64, 2), 256>>>(W_mu, b_mu, W_lv, b_lv, out);
}

// round 16
// speedup vs baseline: 1.0933x; 1.0933x over previous
#include <cuda_runtime.h>
#include <cuda_fp16.h>
#include <cstdint>
#include <math.h>

#define TT 128
#define BB 512
#define DD 300
#define DPAD 320
#define HH 512
#define G3 1536

#define SO_A   0
#define SO_BHI 16384
#define SO_BLO 40960
#define STAGE  65536
#define SMEM_GI (3 * STAGE)

#define PSO_W   0
#define PSO_WLO 98304
#define PSO_A   196608
#define SMEM_P  229376

__device__ __forceinline__ uint32_t smem_u32(const void* p) {
    uint32_t a;
    asm("{ .reg .u64 t; cvta.to.shared.u64 t, %1; cvt.u32.u64 %0, t; }" : "=r"(a) : "l"(p));
    return a;
}
__device__ __forceinline__ void cp16(uint32_t s, const void* g) {
    asm volatile("cp.async.cg.shared.global [%0], [%1], 16;" :: "r"(s), "l"(g));
}
__device__ __forceinline__ void ldm4(uint32_t* r, uint32_t a) {
    asm volatile("ldmatrix.sync.aligned.m8n8.x4.shared.b16 {%0,%1,%2,%3}, [%4];"
                 : "=r"(r[0]), "=r"(r[1]), "=r"(r[2]), "=r"(r[3]) : "r"(a));
}
__device__ __forceinline__ void mma16816(float* c, const uint32_t* a, const uint32_t* b) {
    asm volatile("mma.sync.aligned.m16n8k16.row.col.f32.f16.f16.f32 "
        "{%0,%1,%2,%3}, {%4,%5,%6,%7}, {%8,%9}, {%0,%1,%2,%3};"
        : "+f"(c[0]), "+f"(c[1]), "+f"(c[2]), "+f"(c[3])
        : "r"(a[0]), "r"(a[1]), "r"(a[2]), "r"(a[3]), "r"(b[0]), "r"(b[1]));
}
__device__ __forceinline__ uint32_t swz(uint32_t o) { return o ^ ((o >> 3) & 0x70); }
__device__ __forceinline__ float sigmoidf_(float x) { return 1.f / (1.f + expf(-x)); }

__device__ __align__(16) __half g_x[(size_t)TT * BB * DPAD];
__device__ __align__(16) __half g_Wih0[2][2][(size_t)G3 * DPAD];
__device__ __align__(16) __half g_Wih[2][2][2][(size_t)G3 * HH];
__device__ __align__(16) __half g_Whh[2][3][2][(size_t)G3 * HH];   // 96-row gate perm
__device__ float g_bih[2][3][G3];
__device__ float g_bhh[2][3][G3];
__device__ __align__(16) __half g_h[2][(size_t)TT * BB * HH];
__device__ __align__(16) float g_gi[2][(size_t)TT * BB * G3];
__device__ unsigned g_ctrs[8 * 32];   // one counter per (dir,mblk), 128B apart

// ---------------- prep ----------------
__global__ void prep_x(const float* __restrict__ src) {
    if (blockIdx.x == 0 && threadIdx.x < 8 * 32) g_ctrs[threadIdx.x] = 0;
    const size_t total = (size_t)TT * BB * DPAD;
    for (size_t i = (size_t)blockIdx.x * blockDim.x + threadIdx.x; i < total;
         i += (size_t)gridDim.x * blockDim.x) {
        int r = (int)(i / DPAD), k = (int)(i % DPAD);
        g_x[i] = __float2half_rn((k < DD) ? src[(size_t)r * DD + k] : 0.f);
    }
}

__global__ void prep_w_all(
    const float* __restrict__ fWih0, const float* __restrict__ bWih0,
    const float* __restrict__ fWih,  const float* __restrict__ bWih,
    const float* __restrict__ fWhh0, const float* __restrict__ bWhh0,
    const float* __restrict__ fWhh,  const float* __restrict__ bWhh)
{
    const int ti = blockIdx.y;
    const float* src; int dir, kind, l;
    switch (ti) {
        case 0:  src = fWih0;              dir = 0; kind = 0; l = 0; break;
        case 1:  src = bWih0;              dir = 1; kind = 0; l = 0; break;
        case 2:  src = fWih;               dir = 0; kind = 1; l = 0; break;
        case 3:  src = fWih + (size_t)G3 * HH; dir = 0; kind = 1; l = 1; break;
        case 4:  src = bWih;               dir = 1; kind = 1; l = 0; break;
        case 5:  src = bWih + (size_t)G3 * HH; dir = 1; kind = 1; l = 1; break;
        case 6:  src = fWhh0;              dir = 0; kind = 2; l = 0; break;
        case 7:  src = fWhh;               dir = 0; kind = 2; l = 1; break;
        case 8:  src = fWhh + (size_t)G3 * HH; dir = 0; kind = 2; l = 2; break;
        case 9:  src = bWhh0;              dir = 1; kind = 2; l = 0; break;
        case 10: src = bWhh;               dir = 1; kind = 2; l = 1; break;
        default: src = bWhh + (size_t)G3 * HH; dir = 1; kind = 2; l = 2; break;
    }
    int K, Kpad; __half *hi, *lo;
    if (kind == 0)      { K = DD; Kpad = DPAD; hi = g_Wih0[dir][0]; lo = g_Wih0[dir][1]; }
    else if (kind == 1) { K = HH; Kpad = HH;   hi = g_Wih[dir][l][0]; lo = g_Wih[dir][l][1]; }
    else                { K = HH; Kpad = HH;   hi = g_Whh[dir][l][0]; lo = g_Whh[dir][l][1]; }
    const size_t total = (size_t)G3 * Kpad;
    for (size_t i = (size_t)blockIdx.x * blockDim.x + threadIdx.x; i < total;
         i += (size_t)gridDim.x * blockDim.x) {
        int r = (int)(i / Kpad), k = (int)(i % Kpad);
        int sr;
        if (kind == 2) { int rem = r % 96;  sr = (rem >> 5) * HH + (r / 96) * 32 + (rem & 31); }
        else           { int rem = r % 192; sr = (rem >> 6) * HH + (r / 192) * 64 + (rem & 63); }
        float v = (k < K) ? src[(size_t)sr * K + k] : 0.f;
        __half h = __float2half_rn(v);
        hi[i] = h; lo[i] = __float2half_rn(v - __half2float(h));
    }
}

__global__ void prep_b_all(
    const float* __restrict__ fbih0, const float* __restrict__ bbih0,
    const float* __restrict__ fbih,  const float* __restrict__ bbih,
    const float* __restrict__ fbhh0, const float* __restrict__ bbhh0,
    const float* __restrict__ fbhh,  const float* __restrict__ bbhh)
{
    const int ti = blockIdx.y;
    const int which = ti / 6;
    const int dir = (ti % 6) / 3, l = ti % 3;
    const float* src;
    if (which == 0) {
        if (l == 0) src = dir ? bbih0 : fbih0;
        else        src = (dir ? bbih : fbih) + (size_t)(l - 1) * G3;
    } else {
        if (l == 0) src = dir ? bbhh0 : fbhh0;
        else        src = (dir ? bbhh : fbhh) + (size_t)(l - 1) * G3;
    }
    int r = blockIdx.x * blockDim.x + threadIdx.x;
    if (r < G3) {
        int rem = r % 192;
        float v = src[(rem >> 6) * HH + (r / 192) * 64 + (rem & 63)];
        if (which == 0) g_bih[dir][l][r] = v; else g_bhh[dir][l][r] = v;
    }
}

// ================= gi GEMM path (unchanged from R14) =================
__device__ __forceinline__ void load_tile(
    uint32_t sbuf, const char* A, size_t lda,
    const char* Wh, const char* Wl, size_t ldw, int kt, int tid)
{
    const size_t kb = (size_t)kt * 128;
    for (int i = tid; i < 1024; i += 512) {
        int r = i >> 3, ch = (i & 7) * 16;
        uint32_t so = swz((uint32_t)(r * 128 + ch));
        cp16(sbuf + SO_A + so, A + (size_t)r * lda + kb + ch);
    }
    for (int i = tid; i < 1536; i += 512) {
        int r = i >> 3, ch = (i & 7) * 16;
        uint32_t so = swz((uint32_t)(r * 128 + ch));
        const size_t go = (size_t)r * ldw + kb + ch;
        cp16(sbuf + SO_BHI + so, Wh + go);
        cp16(sbuf + SO_BLO + so, Wl + go);
    }
    asm volatile("cp.async.commit_group;" ::: "memory");
}

__device__ __forceinline__ void compute_tile(
    uint32_t sbuf, int wm, int wn, int lane, float (&acc)[2][3][2][4])
{
    const int arow = wm * 32 + (lane & 15);
    const int acolsel = (lane >> 4) * 16;
    const int mat = lane >> 3;
    const int brow_in = (mat >> 1) * 8 + (lane & 7);
    const int bcol = (mat & 1) * 16;
    #pragma unroll
    for (int kk = 0; kk < 4; kk++) {
        uint32_t ah[2][4];
        #pragma unroll
        for (int mt = 0; mt < 2; mt++) {
            uint32_t o = swz((uint32_t)((arow + mt * 16) * 128 + kk * 32 + acolsel));
            ldm4(ah[mt], sbuf + SO_A + o);
        }
        #pragma unroll
        for (int g = 0; g < 3; g++) {
            uint32_t o = swz((uint32_t)((g * 64 + wn * 16 + brow_in) * 128 + kk * 32 + bcol));
            uint32_t bh[4], bl[4];
            ldm4(bh, sbuf + SO_BHI + o);
            ldm4(bl, sbuf + SO_BLO + o);
            #pragma unroll
            for (int mt = 0; mt < 2; mt++) {
                #pragma unroll
                for (int q = 0; q < 2; q++) {
                    float* c = acc[mt][g][q];
                    mma16816(c, ah[mt], &bh[q * 2]);
                    mma16816(c, ah[mt], &bl[q * 2]);
                }
            }
        }
    }
}

__global__ __launch_bounds__(512) void gi_mma(int l)
{
    extern __shared__ char smem[];
    const uint32_t sb = smem_u32(smem);
    const int tid = threadIdx.x, lane = tid & 31, wid = tid >> 5;
    const int wm = wid & 3, wn = wid >> 2;
    const int dir = blockIdx.z, nblk = blockIdx.x, m0 = blockIdx.y * 128;

    const __half *A, *Wh, *Wl;
    int ld, NK; size_t arow0;
    if (l == 0) {
        ld = DPAD; NK = 5;
        int t = m0 / BB, tt = dir ? (TT - 1 - t) : t;
        arow0 = (size_t)tt * BB + (m0 % BB);
        A = g_x; Wh = g_Wih0[dir][0]; Wl = g_Wih0[dir][1];
    } else {
        ld = HH; NK = 8; arow0 = m0;
        A = g_h[dir];
        Wh = g_Wih[dir][l - 1][0]; Wl = g_Wih[dir][l - 1][1];
    }
    const size_t ldb = (size_t)ld * 2;
    const char* Ab  = (const char*)(A + arow0 * ld);
    const char* Whb = (const char*)(Wh + (size_t)nblk * 192 * ld);
    const char* Wlb = (const char*)(Wl + (size_t)nblk * 192 * ld);

    float acc[2][3][2][4];
    #pragma unroll
    for (int a = 0; a < 2; a++)
        #pragma unroll
        for (int b = 0; b < 3; b++)
            #pragma unroll
            for (int c = 0; c < 2; c++)
                #pragma unroll
                for (int d = 0; d < 4; d++) acc[a][b][c][d] = 0.f;

    uint32_t sstage[3] = { sb, sb + STAGE, sb + 2 * STAGE };
    load_tile(sstage[0], Ab, ldb, Whb, Wlb, ldb, 0, tid);
    load_tile(sstage[1], Ab, ldb, Whb, Wlb, ldb, 1, tid);
    int slot = 0;
    for (int kt = 0; kt < NK; kt++) {
        if (kt + 1 < NK) asm volatile("cp.async.wait_group 1;" ::: "memory");
        else             asm volatile("cp.async.wait_group 0;" ::: "memory");
        __syncthreads();
        if (kt + 2 < NK) {
            int ns = slot + 2; if (ns >= 3) ns -= 3;
            load_tile(sstage[ns], Ab, ldb, Whb, Wlb, ldb, kt + 2, tid);
        }
        compute_tile(sstage[slot], wm, wn, lane, acc);
        if (++slot == 3) slot = 0;
    }

    float* gout = g_gi[dir];
    const float* bias = g_bih[dir][l];
    #pragma unroll
    for (int mt = 0; mt < 2; mt++) {
        const int r0 = m0 + wm * 32 + mt * 16 + (lane >> 2);
        #pragma unroll
        for (int g = 0; g < 3; g++)
            #pragma unroll
            for (int q = 0; q < 2; q++) {
                const int col = nblk * 192 + g * 64 + wn * 16 + q * 8 + (lane & 3) * 2;
                const float b0 = bias[col], b1 = bias[col + 1];
                const float* c = acc[mt][g][q];
                *(float2*)(gout + (size_t)r0 * G3 + col) = make_float2(c[0] + b0, c[1] + b1);
                *(float2*)(gout + (size_t)(r0 + 8) * G3 + col) = make_float2(c[2] + b0, c[3] + b1);
            }
    }
}

// ================= persistent recurrent kernel (R14 + ldm4 B-pairing) ================
__device__ __forceinline__ void p_loadA_grp(uint32_t abuf, const char* Ab, int kt, int gidx)
{
    const size_t kb = (size_t)kt * 128;
    #pragma unroll
    for (int j = 0; j < 2; j++) {
        int i = gidx + j * 128;
        int r = i >> 3, ch = (i & 7) * 16;
        cp16(abuf + swz((uint32_t)(r * 128 + ch)), Ab + (size_t)r * 1024 + kb + ch);
    }
    asm volatile("cp.async.commit_group;" ::: "memory");
}

// B fetched as kk-pair ldm4: regs {0,1}=kk even half, {2,3}=kk odd half
__device__ __forceinline__ void p_compute(
    uint32_t sb, uint32_t abuf, int kt, int wn, int lane, float (&acc)[2][3][4])
{
    const int arow = lane & 15;
    const int acolsel = (lane >> 4) * 16;
    const int bmrow = lane & 7;
    const int bmoff = (lane >> 3) * 16;          // 0,16,32,48 bytes per matrix
    const uint32_t whi = sb + PSO_W   + kt * 12288;
    const uint32_t wlo = sb + PSO_WLO + kt * 12288;
    #pragma unroll
    for (int kp = 0; kp < 2; kp++) {             // kk = 2kp, 2kp+1
        uint32_t ah[2][2][4];
        #pragma unroll
        for (int kq = 0; kq < 2; kq++) {
            const int kk = kp * 2 + kq;
            #pragma unroll
            for (int mt = 0; mt < 2; mt++) {
                uint32_t o = swz((uint32_t)((arow + mt * 16) * 128 + kk * 32 + acolsel));
                ldm4(ah[kq][mt], abuf + o);
            }
        }
        #pragma unroll
        for (int g = 0; g < 3; g++) {
            uint32_t o = swz((uint32_t)((g * 32 + wn * 8 + bmrow) * 128 + kp * 64 + bmoff));
            uint32_t bh[4], bl[4];
            ldm4(bh, whi + o);
            ldm4(bl, wlo + o);
            #pragma unroll
            for (int kq = 0; kq < 2; kq++)
                #pragma unroll
                for (int mt = 0; mt < 2; mt++) {
                    float* c = acc[mt][g];
                    mma16816(c, ah[kq][mt], &bh[kq * 2]);
                    mma16816(c, ah[kq][mt], &bl[kq * 2]);
                }
        }
    }
}

__device__ __forceinline__ void p_prefetch(
    int dir, int t, int m0, int wm, int lane, int j0, int c0,
    float2 (&Pr)[2][2], float2 (&Pz)[2][2], float2 (&Pn)[2][2], __half2 (&Pp)[2][2])
{
    const float* giP = g_gi[dir] + (size_t)t * BB * G3;
    const __half* Ph = g_h[dir] + (size_t)(t - 1) * BB * HH;
    #pragma unroll
    for (int mt = 0; mt < 2; mt++)
        #pragma unroll
        for (int hf = 0; hf < 2; hf++) {
            const int m = m0 + wm * 32 + mt * 16 + (lane >> 2) + hf * 8;
            const float* gim = giP + (size_t)m * G3;
            Pr[mt][hf] = __ldg((const float2*)(gim + c0));
            Pz[mt][hf] = __ldg((const float2*)(gim + c0 + 64));
            Pn[mt][hf] = __ldg((const float2*)(gim + c0 + 128));
            if (t > 0)
                Pp[mt][hf] = __ldg((const __half2*)(Ph + (size_t)m * HH + j0));
            else
                Pp[mt][hf] = __half2{__half(0.f), __half(0.f)};
        }
}

__global__ __launch_bounds__(512) void gru_persist(int l, unsigned base)
{
    extern __shared__ char smem[];
    const uint32_t sb = smem_u32(smem);
    const int tid = threadIdx.x, lane = tid & 31, wid = tid >> 5;
    const int wm = wid & 3, wn = wid >> 2;
    const int gidx = wn * 32 + lane;
    const int barid = 1 + wm;
    const int bid = blockIdx.x;
    const int dir = bid >> 6, nblk = (bid >> 2) & 15, mblk = bid & 3;
    const int m0 = mblk * 128;
    const int grp = dir * 4 + mblk;
    unsigned* ctr = &g_ctrs[grp * 32];
    const bool gleader = (wn == 0 && lane == 0);   // one per wm-group

    // ---- load resident W slice ----
    {
        const char* Wh = (const char*)(g_Whh[dir][l][0] + (size_t)nblk * 96 * HH);
        const char* Wl = (const char*)(g_Whh[dir][l][1] + (size_t)nblk * 96 * HH);
        for (int kt = 0; kt < 8; kt++) {
            for (int i = tid; i < 768; i += 512) {
                int r = i >> 3, ch = (i & 7) * 16;
                uint32_t so = swz((uint32_t)(r * 128 + ch));
                size_t go = (size_t)r * 1024 + (size_t)kt * 128 + ch;
                cp16(sb + PSO_W   + kt * 12288 + so, Wh + go);
                cp16(sb + PSO_WLO + kt * 12288 + so, Wl + go);
            }
        }
        asm volatile("cp.async.commit_group;" ::: "memory");
        asm volatile("cp.async.wait_group 0;" ::: "memory");
        __syncthreads();
    }

    const float* bh = g_bhh[dir][l];
    const int j0 = nblk * 32 + wn * 8 + (lane & 3) * 2;
    const int c0 = ((j0 >> 6) * 192) + (j0 & 63);
    const float bhr0 = bh[c0], bhr1 = bh[c0 + 1];
    const float bhz0 = bh[c0 + 64], bhz1 = bh[c0 + 65];
    const float bhn0 = bh[c0 + 128], bhn1 = bh[c0 + 129];

    const uint32_t agrp = sb + PSO_A + wm * 8192;

    float2 Pr[2][2], Pz[2][2], Pn[2][2];
    __half2 Pp[2][2];
    p_prefetch(dir, 0, m0, wm, lane, j0, c0, Pr, Pz, Pn, Pp);

    for (int t = 0; t < TT; t++) {
        float acc[2][3][4];
        #pragma unroll
        for (int a = 0; a < 2; a++)
            #pragma unroll
            for (int b = 0; b < 3; b++)
                #pragma unroll
                for (int d = 0; d < 4; d++) acc[a][b][d] = 0.f;

        if (t > 0) {
            // consume gate at wm-group scope (acquire by group leader, then group bar)
            if (gleader) {
                const unsigned tgt = base + (unsigned)t * 16u;
                unsigned v;
                while (true) {
                    asm volatile("ld.global.acquire.gpu.u32 %0, [%1];"
                                 : "=r"(v) : "l"(ctr));
                    if (v >= tgt) break;
                    __nanosleep(64);
                }
            }
            asm volatile("bar.sync %0, 128;" :: "r"(barid) : "memory");

            const char* Ab = (const char*)(g_h[dir]
                + ((size_t)(t - 1) * BB + m0 + wm * 32) * HH);
            p_loadA_grp(agrp, Ab, 0, gidx);
            for (int kt = 0; kt < 8; kt++) {
                asm volatile("cp.async.wait_group 0;" ::: "memory");
                asm volatile("bar.sync %0, 128;" :: "r"(barid) : "memory");
                if (kt + 1 < 8)
                    p_loadA_grp(agrp + ((kt + 1) & 1) * 4096, Ab, kt + 1, gidx);
                p_compute(sb, agrp + (kt & 1) * 4096, kt, wn, lane, acc);
            }
        }

        // ---- epilogue ----
        __half* Oh = g_h[dir] + (size_t)t * BB * HH;
        #pragma unroll
        for (int mt = 0; mt < 2; mt++) {
            const float* c_r = acc[mt][0];
            const float* c_z = acc[mt][1];
            const float* c_n = acc[mt][2];
            #pragma unroll
            for (int hf = 0; hf < 2; hf++) {
                const int m = m0 + wm * 32 + mt * 16 + (lane >> 2) + hf * 8;
                const float2 gr = Pr[mt][hf];
                const float2 gz = Pz[mt][hf];
                const float2 gn = Pn[mt][hf];
                const float hp0 = __half2float(Pp[mt][hf].x);
                const float hp1 = __half2float(Pp[mt][hf].y);
                const float rg0 = sigmoidf_(gr.x + bhr0 + c_r[hf * 2 + 0]);
                const float rg1 = sigmoidf_(gr.y + bhr1 + c_r[hf * 2 + 1]);
                const float zg0 = sigmoidf_(gz.x + bhz0 + c_z[hf * 2 + 0]);
                const float zg1 = sigmoidf_(gz.y + bhz1 + c_z[hf * 2 + 1]);
                const float ng0 = tanhf(gn.x + rg0 * (c_n[hf * 2 + 0] + bhn0));
                const float ng1 = tanhf(gn.y + rg1 * (c_n[hf * 2 + 1] + bhn1));
                __half2 hh;
                hh.x = __float2half_rn((1.f - zg0) * ng0 + zg0 * hp0);
                hh.y = __float2half_rn((1.f - zg1) * ng1 + zg1 * hp1);
                *(__half2*)(Oh + (size_t)m * HH + j0) = hh;
            }
        }

        // ---- publish h(t): single CTA-wide sync + release-add; prefetch after ----
        if (t + 1 < TT) {
            __syncthreads();
            if (tid == 0) {
                __threadfence();
                atomicAdd(ctr, 1u);
            }
            p_prefetch(dir, t + 1, m0, wm, lane, j0, c0, Pr, Pz, Pn, Pp);
        }
    }
}

// ---------------- projection ----------------
__global__ __launch_bounds__(256) void proj_kernel(
    const float* __restrict__ Wmu, const float* __restrict__ bmu,
    const float* __restrict__ Wlv, const float* __restrict__ blv,
    float* __restrict__ out)
{
    __shared__ float As[16][66];
    __shared__ float Bs[16][66];
    const int which = blockIdx.z;
    const float* W = which ? Wlv : Wmu;
    const float* bias = which ? blv : bmu;
    const int n0 = blockIdx.x * 64, m0 = blockIdx.y * 64;
    const __half* hf = g_h[0] + ((size_t)(TT - 1) * BB + m0) * HH;
    const __half* hb = g_h[1] + ((size_t)(TT - 1) * BB + m0) * HH;
    const int tid = threadIdx.x, tx = tid & 15, ty = tid >> 4;
    float acc[4][4];
    #pragma unroll
    for (int i = 0; i < 4; i++)
        #pragma unroll
        for (int j = 0; j < 4; j++) acc[i][j] = 0.f;

    for (int k0 = 0; k0 < 2 * HH; k0 += 16) {
        #pragma unroll
        for (int i = 0; i < 4; i++) {
            const int e = tid + i * 256;
            const int kk = e & 15, mm = e >> 4;
            const int k = k0 + kk;
            As[kk][mm] = (k < HH) ? __half2float(hf[(size_t)mm * HH + k])
                                  : __half2float(hb[(size_t)mm * HH + k - HH]);
            Bs[kk][mm] = W[(size_t)(n0 + mm) * (2 * HH) + k];
        }
        __syncthreads();
        #pragma unroll
        for (int kk = 0; kk < 16; kk++) {
            float a[4], b[4];
            #pragma unroll
            for (int i = 0; i < 4; i++) a[i] = As[kk][ty * 4 + i];
            #pragma unroll
            for (int j = 0; j < 4; j++) b[j] = Bs[kk][tx * 4 + j];
            #pragma unroll
            for (int i = 0; i < 4; i++)
                #pragma unroll
                for (int j = 0; j < 4; j++) acc[i][j] += a[i] * b[j];
        }
        __syncthreads();
    }
    #pragma unroll
    for (int i = 0; i < 4; i++) {
        const int m = m0 + ty * 4 + i;
        #pragma unroll
        for (int j = 0; j < 4; j++) {
            const int n = n0 + tx * 4 + j;
            out[(size_t)which * BB * HH + (size_t)m * HH + n] = acc[i][j] + bias[n];
        }
    }
}

extern "C" void kernel_launch(void* const* d_in, const int* in_sizes, int n_in,
                              void* d_out, int out_size)
{
    (void)in_sizes; (void)n_in; (void)out_size;
    const float* x       = (const float*)d_in[0];
    const float* fw_Wih0 = (const float*)d_in[2];
    const float* fw_Whh0 = (const float*)d_in[3];
    const float* fw_bih0 = (const float*)d_in[4];
    const float* fw_bhh0 = (const float*)d_in[5];
    const float* fw_Wih  = (const float*)d_in[6];
    const float* fw_Whh  = (const float*)d_in[7];
    const float* fw_bih  = (const float*)d_in[8];
    const float* fw_bhh  = (const float*)d_in[9];
    const float* bw_Wih0 = (const float*)d_in[10];
    const float* bw_Whh0 = (const float*)d_in[11];
    const float* bw_bih0 = (const float*)d_in[12];
    const float* bw_bhh0 = (const float*)d_in[13];
    const float* bw_Wih  = (const float*)d_in[14];
    const float* bw_Whh  = (const float*)d_in[15];
    const float* bw_bih  = (const float*)d_in[16];
    const float* bw_bhh  = (const float*)d_in[17];
    const float* W_mu    = (const float*)d_in[18];
    const float* b_mu    = (const float*)d_in[19];
    const float* W_lv    = (const float*)d_in[20];
    const float* b_lv    = (const float*)d_in[21];
    float* out = (float*)d_out;

    cudaFuncSetAttribute(gi_mma,      cudaFuncAttributeMaxDynamicSharedMemorySize, SMEM_GI);
    cudaFuncSetAttribute(gru_persist, cudaFuncAttributeMaxDynamicSharedMemorySize, SMEM_P);

    prep_x<<<2048, 256>>>(x);
    prep_w_all<<<dim3(256, 12), 256>>>(fw_Wih0, bw_Wih0, fw_Wih, bw_Wih,
                                       fw_Whh0, bw_Whh0, fw_Whh, bw_Whh);
    prep_b_all<<<dim3(6, 12), 256>>>(fw_bih0, bw_bih0, fw_bih, bw_bih,
                                     fw_bhh0, bw_bhh0, fw_bhh, bw_bhh);

    const dim3 ggi(8, (TT * BB) / 128, 2);
    for (int l = 0; l < 3; l++) {
        gi_mma<<<ggi, 512, SMEM_GI>>>(l);
        gru_persist<<<128, 512, SMEM_P>>>(l, (unsigned)(l * 127 * 16));
    }
    proj_kernel<<<dim3(HH / 64, BB / 64, 2), 256>>>(W_mu, b_mu, W_lv, b_lv, out);
}

// round 17
// speedup vs baseline: 1.1509x; 1.0526x over previous
#include <cuda_runtime.h>
#include <cuda_fp16.h>
#include <cstdint>
#include <math.h>

#define TT 128
#define BB 512
#define DD 300
#define DPAD 320
#define HH 512
#define G3 1536

#define SO_A   0
#define SO_BHI 16384
#define SO_BLO 40960
#define STAGE  65536
#define SMEM_GI (3 * STAGE)

#define PSO_W   0
#define PSO_WLO 98304
#define PSO_A   196608
#define SMEM_P  229376

__device__ __forceinline__ uint32_t smem_u32(const void* p) {
    uint32_t a;
    asm("{ .reg .u64 t; cvta.to.shared.u64 t, %1; cvt.u32.u64 %0, t; }" : "=r"(a) : "l"(p));
    return a;
}
__device__ __forceinline__ void cp16(uint32_t s, const void* g) {
    asm volatile("cp.async.cg.shared.global [%0], [%1], 16;" :: "r"(s), "l"(g));
}
__device__ __forceinline__ void ldm4(uint32_t* r, uint32_t a) {
    asm volatile("ldmatrix.sync.aligned.m8n8.x4.shared.b16 {%0,%1,%2,%3}, [%4];"
                 : "=r"(r[0]), "=r"(r[1]), "=r"(r[2]), "=r"(r[3]) : "r"(a));
}
__device__ __forceinline__ void mma16816(float* c, const uint32_t* a, const uint32_t* b) {
    asm volatile("mma.sync.aligned.m16n8k16.row.col.f32.f16.f16.f32 "
        "{%0,%1,%2,%3}, {%4,%5,%6,%7}, {%8,%9}, {%0,%1,%2,%3};"
        : "+f"(c[0]), "+f"(c[1]), "+f"(c[2]), "+f"(c[3])
        : "r"(a[0]), "r"(a[1]), "r"(a[2]), "r"(a[3]), "r"(b[0]), "r"(b[1]));
}
__device__ __forceinline__ uint32_t swz(uint32_t o) { return o ^ ((o >> 3) & 0x70); }
__device__ __forceinline__ float sigmoidf_(float x) { return 1.f / (1.f + expf(-x)); }

__device__ __align__(16) __half g_x[(size_t)TT * BB * DPAD];
__device__ __align__(16) __half g_Wih0[2][2][(size_t)G3 * DPAD];
__device__ __align__(16) __half g_Wih[2][2][2][(size_t)G3 * HH];
__device__ __align__(16) __half g_Whh[2][3][2][(size_t)G3 * HH];   // 96-row gate perm
__device__ float g_bih[2][3][G3];
__device__ float g_bhh[2][3][G3];
__device__ __align__(16) __half g_h[2][(size_t)TT * BB * HH];
__device__ __align__(16) float g_gi[2][(size_t)TT * BB * G3];
__device__ unsigned g_ctrs[8 * 32];   // one counter per (dir,mblk), 128B apart

// ---------------- prep ----------------
__global__ void prep_x(const float* __restrict__ src) {
    if (blockIdx.x == 0 && threadIdx.x < 8 * 32) g_ctrs[threadIdx.x] = 0;
    const size_t total = (size_t)TT * BB * DPAD;
    for (size_t i = (size_t)blockIdx.x * blockDim.x + threadIdx.x; i < total;
         i += (size_t)gridDim.x * blockDim.x) {
        int r = (int)(i / DPAD), k = (int)(i % DPAD);
        g_x[i] = __float2half_rn((k < DD) ? src[(size_t)r * DD + k] : 0.f);
    }
}

// y = 0..11: weight tensors; y = 12: all biases
__global__ void prep_wb_all(
    const float* __restrict__ fWih0, const float* __restrict__ bWih0,
    const float* __restrict__ fWih,  const float* __restrict__ bWih,
    const float* __restrict__ fWhh0, const float* __restrict__ bWhh0,
    const float* __restrict__ fWhh,  const float* __restrict__ bWhh,
    const float* __restrict__ fbih0, const float* __restrict__ bbih0,
    const float* __restrict__ fbih,  const float* __restrict__ bbih,
    const float* __restrict__ fbhh0, const float* __restrict__ bbhh0,
    const float* __restrict__ fbhh,  const float* __restrict__ bbhh)
{
    const int ti = blockIdx.y;
    if (ti == 12) {
        // biases: 12 tensors x G3 each
        for (int idx = blockIdx.x * blockDim.x + threadIdx.x; idx < 12 * G3;
             idx += gridDim.x * blockDim.x) {
            const int bt = idx / G3, r = idx % G3;
            const int which = bt / 6, dir = (bt % 6) / 3, l = bt % 3;
            const float* src;
            if (which == 0) {
                if (l == 0) src = dir ? bbih0 : fbih0;
                else        src = (dir ? bbih : fbih) + (size_t)(l - 1) * G3;
            } else {
                if (l == 0) src = dir ? bbhh0 : fbhh0;
                else        src = (dir ? bbhh : fbhh) + (size_t)(l - 1) * G3;
            }
            int rem = r % 192;
            float v = src[(rem >> 6) * HH + (r / 192) * 64 + (rem & 63)];
            if (which == 0) g_bih[dir][l][r] = v; else g_bhh[dir][l][r] = v;
        }
        return;
    }
    const float* src; int dir, kind, l;
    switch (ti) {
        case 0:  src = fWih0;              dir = 0; kind = 0; l = 0; break;
        case 1:  src = bWih0;              dir = 1; kind = 0; l = 0; break;
        case 2:  src = fWih;               dir = 0; kind = 1; l = 0; break;
        case 3:  src = fWih + (size_t)G3 * HH; dir = 0; kind = 1; l = 1; break;
        case 4:  src = bWih;               dir = 1; kind = 1; l = 0; break;
        case 5:  src = bWih + (size_t)G3 * HH; dir = 1; kind = 1; l = 1; break;
        case 6:  src = fWhh0;              dir = 0; kind = 2; l = 0; break;
        case 7:  src = fWhh;               dir = 0; kind = 2; l = 1; break;
        case 8:  src = fWhh + (size_t)G3 * HH; dir = 0; kind = 2; l = 2; break;
        case 9:  src = bWhh0;              dir = 1; kind = 2; l = 0; break;
        case 10: src = bWhh;               dir = 1; kind = 2; l = 1; break;
        default: src = bWhh + (size_t)G3 * HH; dir = 1; kind = 2; l = 2; break;
    }
    int K, Kpad; __half *hi, *lo;
    if (kind == 0)      { K = DD; Kpad = DPAD; hi = g_Wih0[dir][0]; lo = g_Wih0[dir][1]; }
    else if (kind == 1) { K = HH; Kpad = HH;   hi = g_Wih[dir][l][0]; lo = g_Wih[dir][l][1]; }
    else                { K = HH; Kpad = HH;   hi = g_Whh[dir][l][0]; lo = g_Whh[dir][l][1]; }
    const size_t total = (size_t)G3 * Kpad;
    for (size_t i = (size_t)blockIdx.x * blockDim.x + threadIdx.x; i < total;
         i += (size_t)gridDim.x * blockDim.x) {
        int r = (int)(i / Kpad), k = (int)(i % Kpad);
        int sr;
        if (kind == 2) { int rem = r % 96;  sr = (rem >> 5) * HH + (r / 96) * 32 + (rem & 31); }
        else           { int rem = r % 192; sr = (rem >> 6) * HH + (r / 192) * 64 + (rem & 63); }
        float v = (k < K) ? src[(size_t)sr * K + k] : 0.f;
        __half h = __float2half_rn(v);
        hi[i] = h; lo[i] = __float2half_rn(v - __half2float(h));
    }
}

// ================= gi GEMM path (unchanged) =================
__device__ __forceinline__ void load_tile(
    uint32_t sbuf, const char* A, size_t lda,
    const char* Wh, const char* Wl, size_t ldw, int kt, int tid)
{
    const size_t kb = (size_t)kt * 128;
    for (int i = tid; i < 1024; i += 512) {
        int r = i >> 3, ch = (i & 7) * 16;
        uint32_t so = swz((uint32_t)(r * 128 + ch));
        cp16(sbuf + SO_A + so, A + (size_t)r * lda + kb + ch);
    }
    for (int i = tid; i < 1536; i += 512) {
        int r = i >> 3, ch = (i & 7) * 16;
        uint32_t so = swz((uint32_t)(r * 128 + ch));
        const size_t go = (size_t)r * ldw + kb + ch;
        cp16(sbuf + SO_BHI + so, Wh + go);
        cp16(sbuf + SO_BLO + so, Wl + go);
    }
    asm volatile("cp.async.commit_group;" ::: "memory");
}

__device__ __forceinline__ void compute_tile(
    uint32_t sbuf, int wm, int wn, int lane, float (&acc)[2][3][2][4])
{
    const int arow = wm * 32 + (lane & 15);
    const int acolsel = (lane >> 4) * 16;
    const int mat = lane >> 3;
    const int brow_in = (mat >> 1) * 8 + (lane & 7);
    const int bcol = (mat & 1) * 16;
    #pragma unroll
    for (int kk = 0; kk < 4; kk++) {
        uint32_t ah[2][4];
        #pragma unroll
        for (int mt = 0; mt < 2; mt++) {
            uint32_t o = swz((uint32_t)((arow + mt * 16) * 128 + kk * 32 + acolsel));
            ldm4(ah[mt], sbuf + SO_A + o);
        }
        #pragma unroll
        for (int g = 0; g < 3; g++) {
            uint32_t o = swz((uint32_t)((g * 64 + wn * 16 + brow_in) * 128 + kk * 32 + bcol));
            uint32_t bh[4], bl[4];
            ldm4(bh, sbuf + SO_BHI + o);
            ldm4(bl, sbuf + SO_BLO + o);
            #pragma unroll
            for (int mt = 0; mt < 2; mt++) {
                #pragma unroll
                for (int q = 0; q < 2; q++) {
                    float* c = acc[mt][g][q];
                    mma16816(c, ah[mt], &bh[q * 2]);
                    mma16816(c, ah[mt], &bl[q * 2]);
                }
            }
        }
    }
}

__global__ __launch_bounds__(512) void gi_mma(int l)
{
    extern __shared__ char smem[];
    const uint32_t sb = smem_u32(smem);
    const int tid = threadIdx.x, lane = tid & 31, wid = tid >> 5;
    const int wm = wid & 3, wn = wid >> 2;
    const int dir = blockIdx.z, nblk = blockIdx.x, m0 = blockIdx.y * 128;

    const __half *A, *Wh, *Wl;
    int ld, NK; size_t arow0;
    if (l == 0) {
        ld = DPAD; NK = 5;
        int t = m0 / BB, tt = dir ? (TT - 1 - t) : t;
        arow0 = (size_t)tt * BB + (m0 % BB);
        A = g_x; Wh = g_Wih0[dir][0]; Wl = g_Wih0[dir][1];
    } else {
        ld = HH; NK = 8; arow0 = m0;
        A = g_h[dir];
        Wh = g_Wih[dir][l - 1][0]; Wl = g_Wih[dir][l - 1][1];
    }
    const size_t ldb = (size_t)ld * 2;
    const char* Ab  = (const char*)(A + arow0 * ld);
    const char* Whb = (const char*)(Wh + (size_t)nblk * 192 * ld);
    const char* Wlb = (const char*)(Wl + (size_t)nblk * 192 * ld);

    float acc[2][3][2][4];
    #pragma unroll
    for (int a = 0; a < 2; a++)
        #pragma unroll
        for (int b = 0; b < 3; b++)
            #pragma unroll
            for (int c = 0; c < 2; c++)
                #pragma unroll
                for (int d = 0; d < 4; d++) acc[a][b][c][d] = 0.f;

    uint32_t sstage[3] = { sb, sb + STAGE, sb + 2 * STAGE };
    load_tile(sstage[0], Ab, ldb, Whb, Wlb, ldb, 0, tid);
    load_tile(sstage[1], Ab, ldb, Whb, Wlb, ldb, 1, tid);
    int slot = 0;
    for (int kt = 0; kt < NK; kt++) {
        if (kt + 1 < NK) asm volatile("cp.async.wait_group 1;" ::: "memory");
        else             asm volatile("cp.async.wait_group 0;" ::: "memory");
        __syncthreads();
        if (kt + 2 < NK) {
            int ns = slot + 2; if (ns >= 3) ns -= 3;
            load_tile(sstage[ns], Ab, ldb, Whb, Wlb, ldb, kt + 2, tid);
        }
        compute_tile(sstage[slot], wm, wn, lane, acc);
        if (++slot == 3) slot = 0;
    }

    float* gout = g_gi[dir];
    const float* bias = g_bih[dir][l];
    #pragma unroll
    for (int mt = 0; mt < 2; mt++) {
        const int r0 = m0 + wm * 32 + mt * 16 + (lane >> 2);
        #pragma unroll
        for (int g = 0; g < 3; g++)
            #pragma unroll
            for (int q = 0; q < 2; q++) {
                const int col = nblk * 192 + g * 64 + wn * 16 + q * 8 + (lane & 3) * 2;
                const float b0 = bias[col], b1 = bias[col + 1];
                const float* c = acc[mt][g][q];
                *(float2*)(gout + (size_t)r0 * G3 + col) = make_float2(c[0] + b0, c[1] + b1);
                *(float2*)(gout + (size_t)(r0 + 8) * G3 + col) = make_float2(c[2] + b0, c[3] + b1);
            }
    }
}

// ================= persistent recurrent kernel (R16 + register-carry h) ================
__device__ __forceinline__ void p_loadA_grp(uint32_t abuf, const char* Ab, int kt, int gidx)
{
    const size_t kb = (size_t)kt * 128;
    #pragma unroll
    for (int j = 0; j < 2; j++) {
        int i = gidx + j * 128;
        int r = i >> 3, ch = (i & 7) * 16;
        cp16(abuf + swz((uint32_t)(r * 128 + ch)), Ab + (size_t)r * 1024 + kb + ch);
    }
    asm volatile("cp.async.commit_group;" ::: "memory");
}

__device__ __forceinline__ void p_compute(
    uint32_t sb, uint32_t abuf, int kt, int wn, int lane, float (&acc)[2][3][4])
{
    const int arow = lane & 15;
    const int acolsel = (lane >> 4) * 16;
    const int bmrow = lane & 7;
    const int bmoff = (lane >> 3) * 16;
    const uint32_t whi = sb + PSO_W   + kt * 12288;
    const uint32_t wlo = sb + PSO_WLO + kt * 12288;
    #pragma unroll
    for (int kp = 0; kp < 2; kp++) {
        uint32_t ah[2][2][4];
        #pragma unroll
        for (int kq = 0; kq < 2; kq++) {
            const int kk = kp * 2 + kq;
            #pragma unroll
            for (int mt = 0; mt < 2; mt++) {
                uint32_t o = swz((uint32_t)((arow + mt * 16) * 128 + kk * 32 + acolsel));
                ldm4(ah[kq][mt], abuf + o);
            }
        }
        #pragma unroll
        for (int g = 0; g < 3; g++) {
            uint32_t o = swz((uint32_t)((g * 32 + wn * 8 + bmrow) * 128 + kp * 64 + bmoff));
            uint32_t bh[4], bl[4];
            ldm4(bh, whi + o);
            ldm4(bl, wlo + o);
            #pragma unroll
            for (int kq = 0; kq < 2; kq++)
                #pragma unroll
                for (int mt = 0; mt < 2; mt++) {
                    float* c = acc[mt][g];
                    mma16816(c, ah[kq][mt], &bh[kq * 2]);
                    mma16816(c, ah[kq][mt], &bl[kq * 2]);
                }
        }
    }
}

__device__ __forceinline__ void p_prefetch(
    int dir, int t, int m0, int wm, int lane, int c0,
    float2 (&Pr)[2][2], float2 (&Pz)[2][2], float2 (&Pn)[2][2])
{
    const float* giP = g_gi[dir] + (size_t)t * BB * G3;
    #pragma unroll
    for (int mt = 0; mt < 2; mt++)
        #pragma unroll
        for (int hf = 0; hf < 2; hf++) {
            const int m = m0 + wm * 32 + mt * 16 + (lane >> 2) + hf * 8;
            const float* gim = giP + (size_t)m * G3;
            Pr[mt][hf] = __ldg((const float2*)(gim + c0));
            Pz[mt][hf] = __ldg((const float2*)(gim + c0 + 64));
            Pn[mt][hf] = __ldg((const float2*)(gim + c0 + 128));
        }
}

__global__ __launch_bounds__(512) void gru_persist(int l, unsigned base)
{
    extern __shared__ char smem[];
    const uint32_t sb = smem_u32(smem);
    const int tid = threadIdx.x, lane = tid & 31, wid = tid >> 5;
    const int wm = wid & 3, wn = wid >> 2;
    const int gidx = wn * 32 + lane;
    const int barid = 1 + wm;
    const int bid = blockIdx.x;
    const int dir = bid >> 6, nblk = (bid >> 2) & 15, mblk = bid & 3;
    const int m0 = mblk * 128;
    const int grp = dir * 4 + mblk;
    unsigned* ctr = &g_ctrs[grp * 32];
    const bool gleader = (wn == 0 && lane == 0);

    // ---- load resident W slice ----
    {
        const char* Wh = (const char*)(g_Whh[dir][l][0] + (size_t)nblk * 96 * HH);
        const char* Wl = (const char*)(g_Whh[dir][l][1] + (size_t)nblk * 96 * HH);
        for (int kt = 0; kt < 8; kt++) {
            for (int i = tid; i < 768; i += 512) {
                int r = i >> 3, ch = (i & 7) * 16;
                uint32_t so = swz((uint32_t)(r * 128 + ch));
                size_t go = (size_t)r * 1024 + (size_t)kt * 128 + ch;
                cp16(sb + PSO_W   + kt * 12288 + so, Wh + go);
                cp16(sb + PSO_WLO + kt * 12288 + so, Wl + go);
            }
        }
        asm volatile("cp.async.commit_group;" ::: "memory");
        asm volatile("cp.async.wait_group 0;" ::: "memory");
        __syncthreads();
    }

    const float* bh = g_bhh[dir][l];
    const int j0 = nblk * 32 + wn * 8 + (lane & 3) * 2;
    const int c0 = ((j0 >> 6) * 192) + (j0 & 63);
    const float bhr0 = bh[c0], bhr1 = bh[c0 + 1];
    const float bhz0 = bh[c0 + 64], bhz1 = bh[c0 + 65];
    const float bhn0 = bh[c0 + 128], bhn1 = bh[c0 + 129];

    const uint32_t agrp = sb + PSO_A + wm * 8192;

    float2 Pr[2][2], Pz[2][2], Pn[2][2];
    // register-carried h_prev (this thread's own (m, j0) values)
    __half2 hc[2][2];
    #pragma unroll
    for (int mt = 0; mt < 2; mt++)
        #pragma unroll
        for (int hf = 0; hf < 2; hf++) hc[mt][hf] = __half2{__half(0.f), __half(0.f)};

    p_prefetch(dir, 0, m0, wm, lane, c0, Pr, Pz, Pn);

    for (int t = 0; t < TT; t++) {
        float acc[2][3][4];
        #pragma unroll
        for (int a = 0; a < 2; a++)
            #pragma unroll
            for (int b = 0; b < 3; b++)
                #pragma unroll
                for (int d = 0; d < 4; d++) acc[a][b][d] = 0.f;

        if (t > 0) {
            if (gleader) {
                const unsigned tgt = base + (unsigned)t * 16u;
                unsigned v;
                while (true) {
                    asm volatile("ld.global.acquire.gpu.u32 %0, [%1];"
                                 : "=r"(v) : "l"(ctr));
                    if (v >= tgt) break;
                    __nanosleep(64);
                }
            }
            asm volatile("bar.sync %0, 128;" :: "r"(barid) : "memory");

            const char* Ab = (const char*)(g_h[dir]
                + ((size_t)(t - 1) * BB + m0 + wm * 32) * HH);
            p_loadA_grp(agrp, Ab, 0, gidx);
            for (int kt = 0; kt < 8; kt++) {
                asm volatile("cp.async.wait_group 0;" ::: "memory");
                asm volatile("bar.sync %0, 128;" :: "r"(barid) : "memory");
                if (kt + 1 < 8)
                    p_loadA_grp(agrp + ((kt + 1) & 1) * 4096, Ab, kt + 1, gidx);
                p_compute(sb, agrp + (kt & 1) * 4096, kt, wn, lane, acc);
            }
        }

        // ---- epilogue (h_prev from carry registers) ----
        __half* Oh = g_h[dir] + (size_t)t * BB * HH;
        #pragma unroll
        for (int mt = 0; mt < 2; mt++) {
            const float* c_r = acc[mt][0];
            const float* c_z = acc[mt][1];
            const float* c_n = acc[mt][2];
            #pragma unroll
            for (int hf = 0; hf < 2; hf++) {
                const int m = m0 + wm * 32 + mt * 16 + (lane >> 2) + hf * 8;
                const float2 gr = Pr[mt][hf];
                const float2 gz = Pz[mt][hf];
                const float2 gn = Pn[mt][hf];
                const float hp0 = __half2float(hc[mt][hf].x);
                const float hp1 = __half2float(hc[mt][hf].y);
                const float rg0 = sigmoidf_(gr.x + bhr0 + c_r[hf * 2 + 0]);
                const float rg1 = sigmoidf_(gr.y + bhr1 + c_r[hf * 2 + 1]);
                const float zg0 = sigmoidf_(gz.x + bhz0 + c_z[hf * 2 + 0]);
                const float zg1 = sigmoidf_(gz.y + bhz1 + c_z[hf * 2 + 1]);
                const float ng0 = tanhf(gn.x + rg0 * (c_n[hf * 2 + 0] + bhn0));
                const float ng1 = tanhf(gn.y + rg1 * (c_n[hf * 2 + 1] + bhn1));
                __half2 hh;
                hh.x = __float2half_rn((1.f - zg0) * ng0 + zg0 * hp0);
                hh.y = __float2half_rn((1.f - zg1) * ng1 + zg1 * hp1);
                hc[mt][hf] = hh;
                *(__half2*)(Oh + (size_t)m * HH + j0) = hh;
            }
        }

        // ---- publish h(t): single CTA-wide sync + release-add; prefetch after ----
        if (t + 1 < TT) {
            __syncthreads();
            if (tid == 0) {
                __threadfence();
                atomicAdd(ctr, 1u);
            }
            p_prefetch(dir, t + 1, m0, wm, lane, c0, Pr, Pz, Pn);
        }
    }
}

// ---------------- projection ----------------
__global__ __launch_bounds__(256) void proj_kernel(
    const float* __restrict__ Wmu, const float* __restrict__ bmu,
    const float* __restrict__ Wlv, const float* __restrict__ blv,
    float* __restrict__ out)
{
    __shared__ float As[16][66];
    __shared__ float Bs[16][66];
    const int which = blockIdx.z;
    const float* W = which ? Wlv : Wmu;
    const float* bias = which ? blv : bmu;
    const int n0 = blockIdx.x * 64, m0 = blockIdx.y * 64;
    const __half* hf = g_h[0] + ((size_t)(TT - 1) * BB + m0) * HH;
    const __half* hb = g_h[1] + ((size_t)(TT - 1) * BB + m0) * HH;
    const int tid = threadIdx.x, tx = tid & 15, ty = tid >> 4;
    float acc[4][4];
    #pragma unroll
    for (int i = 0; i < 4; i++)
        #pragma unroll
        for (int j = 0; j < 4; j++) acc[i][j] = 0.f;

    for (int k0 = 0; k0 < 2 * HH; k0 += 16) {
        #pragma unroll
        for (int i = 0; i < 4; i++) {
            const int e = tid + i * 256;
            const int kk = e & 15, mm = e >> 4;
            const int k = k0 + kk;
            As[kk][mm] = (k < HH) ? __half2float(hf[(size_t)mm * HH + k])
                                  : __half2float(hb[(size_t)mm * HH + k - HH]);
            Bs[kk][mm] = W[(size_t)(n0 + mm) * (2 * HH) + k];
        }
        __syncthreads();
        #pragma unroll
        for (int kk = 0; kk < 16; kk++) {
            float a[4], b[4];
            #pragma unroll
            for (int i = 0; i < 4; i++) a[i] = As[kk][ty * 4 + i];
            #pragma unroll
            for (int j = 0; j < 4; j++) b[j] = Bs[kk][tx * 4 + j];
            #pragma unroll
            for (int i = 0; i < 4; i++)
                #pragma unroll
                for (int j = 0; j < 4; j++) acc[i][j] += a[i] * b[j];
        }
        __syncthreads();
    }
    #pragma unroll
    for (int i = 0; i < 4; i++) {
        const int m = m0 + ty * 4 + i;
        #pragma unroll
        for (int j = 0; j < 4; j++) {
            const int n = n0 + tx * 4 + j;
            out[(size_t)which * BB * HH + (size_t)m * HH + n] = acc[i][j] + bias[n];
        }
    }
}

extern "C" void kernel_launch(void* const* d_in, const int* in_sizes, int n_in,
                              void* d_out, int out_size)
{
    (void)in_sizes; (void)n_in; (void)out_size;
    const float* x       = (const float*)d_in[0];
    const float* fw_Wih0 = (const float*)d_in[2];
    const float* fw_Whh0 = (const float*)d_in[3];
    const float* fw_bih0 = (const float*)d_in[4];
    const float* fw_bhh0 = (const float*)d_in[5];
    const float* fw_Wih  = (const float*)d_in[6];
    const float* fw_Whh  = (const float*)d_in[7];
    const float* fw_bih  = (const float*)d_in[8];
    const float* fw_bhh  = (const float*)d_in[9];
    const float* bw_Wih0 = (const float*)d_in[10];
    const float* bw_Whh0 = (const float*)d_in[11];
    const float* bw_bih0 = (const float*)d_in[12];
    const float* bw_bhh0 = (const float*)d_in[13];
    const float* bw_Wih  = (const float*)d_in[14];
    const float* bw_Whh  = (const float*)d_in[15];
    const float* bw_bih  = (const float*)d_in[16];
    const float* bw_bhh  = (const float*)d_in[17];
    const float* W_mu    = (const float*)d_in[18];
    const float* b_mu    = (const float*)d_in[19];
    const float* W_lv    = (const float*)d_in[20];
    const float* b_lv    = (const float*)d_in[21];
    float* out = (float*)d_out;

    cudaFuncSetAttribute(gi_mma,      cudaFuncAttributeMaxDynamicSharedMemorySize, SMEM_GI);
    cudaFuncSetAttribute(gru_persist, cudaFuncAttributeMaxDynamicSharedMemorySize, SMEM_P);

    prep_x<<<2048, 256>>>(x);
    prep_wb_all<<<dim3(256, 13), 256>>>(fw_Wih0, bw_Wih0, fw_Wih, bw_Wih,
                                        fw_Whh0, bw_Whh0, fw_Whh, bw_Whh,
                                        fw_bih0, bw_bih0, fw_bih, bw_bih,
                                        fw_bhh0, bw_bhh0, fw_bhh, bw_bhh);

    const dim3 ggi(8, (TT * BB) / 128, 2);
    for (int l = 0; l < 3; l++) {
        gi_mma<<<ggi, 512, SMEM_GI>>>(l);
        gru_persist<<<128, 512, SMEM_P>>>(l, (unsigned)(l * 127 * 16));
    }
    proj_kernel<<<dim3(HH / 64, BB / 64, 2), 256>>>(W_mu, b_mu, W_lv, b_lv, out);
}